// round 4
// baseline (speedup 1.0000x reference)
#include <cuda_runtime.h>
#include <math.h>

#define N_NODES  100000
#define N_EDGES  3200000
#define N_GRAPHS 256
#define CAP      96        // fixed CSR stride; P(in-degree >= 96) ~ e^-50 for Binom(3.2M,1e-5)

// -------- scratch (device globals: no allocations allowed) --------
__device__ int   g_deg[N_NODES];                       // out-degree over row (+1 self)
__device__ int   g_cur[N_NODES];                       // CSR fill cursor -> in-degree
__device__ float g_dis[N_NODES];
__device__ __align__(16) float g_ps[N_NODES * 4];      // {d*p0, d*p1, d*p2, d}
__device__ int   g_csr[N_NODES * CAP];                 // source node per in-edge
__device__ float g_nrm[N_NODES * CAP];                 // norm per in-edge
__device__ __align__(16) float g_h1[N_NODES * 32];
__device__ __align__(16) float g_agg2[N_NODES * 32];
__device__ float g_pooled[N_GRAPHS * 64];

__device__ __forceinline__ void red_add_s32(int* p, int v) {
    asm volatile("red.global.add.s32 [%0], %1;" :: "l"(p), "r"(v) : "memory");
}

// -------- init: deg=1 (self loop), cur=0, pooled=-inf --------
__global__ void k_init() {
    int t = blockIdx.x * blockDim.x + threadIdx.x;
    if (t < N_NODES) { g_deg[t] = 1; g_cur[t] = 0; }
    if (t < N_GRAPHS * 64) reinterpret_cast<int*>(g_pooled)[t] = 0xFF800000;
}

// -------- build: degree count over row + CSR fill by col --------
__global__ void k_build(const int* __restrict__ row, const int* __restrict__ col) {
    int e = blockIdx.x * blockDim.x + threadIdx.x;
    if (e >= N_EDGES) return;
    int r = row[e], c = col[e];
    red_add_s32(&g_deg[r], 1);
    int loc = atomicAdd(&g_cur[c], 1);
    if (loc < CAP) g_csr[c * CAP + loc] = r;
}

// -------- dis + pos_scaled --------
__global__ void k_dis(const float* __restrict__ pos) {
    int i = blockIdx.x * blockDim.x + threadIdx.x;
    if (i >= N_NODES) return;
    float d = rsqrtf((float)g_deg[i]);
    g_dis[i] = d;
    float p0 = pos[i * 3 + 0], p1 = pos[i * 3 + 1], p2 = pos[i * 3 + 2];
    *reinterpret_cast<float4*>(&g_ps[i * 4]) = make_float4(d * p0, d * p1, d * p2, d);
}

// -------- layer 1 gather + transform fused: warp per node --------
__global__ void k_gather1(const float* __restrict__ W1, const float* __restrict__ b1) {
    int w = (blockIdx.x * blockDim.x + threadIdx.x) >> 5;
    int lane = threadIdx.x & 31;
    if (w >= N_NODES) return;
    int i = w;
    int cnt = min(g_cur[i], CAP);
    float dc = g_dis[i];

    float a0 = 0.f, a1 = 0.f, a2 = 0.f;
    for (int j = lane; j < cnt; j += 32) {
        int r = g_csr[i * CAP + j];
        float4 ps = *reinterpret_cast<const float4*>(&g_ps[r * 4]);  // {d_r*p, d_r}
        a0 += ps.x; a1 += ps.y; a2 += ps.z;
        g_nrm[i * CAP + j] = dc * ps.w;          // norm for layer-2 reuse
    }
#pragma unroll
    for (int s = 16; s > 0; s >>= 1) {
        a0 += __shfl_xor_sync(0xffffffff, a0, s);
        a1 += __shfl_xor_sync(0xffffffff, a1, s);
        a2 += __shfl_xor_sync(0xffffffff, a2, s);
    }
    // self loop: norm = dc^2, msg = dc^2 * p_c = dc * ps_c.{x,y,z}
    float4 psc = *reinterpret_cast<const float4*>(&g_ps[i * 4]);
    a0 = dc * (a0 + psc.x);
    a1 = dc * (a1 + psc.y);
    a2 = dc * (a2 + psc.z);

    int o = lane;
    float acc = b1[o] + a0 * W1[o * 3 + 0] + a1 * W1[o * 3 + 1] + a2 * W1[o * 3 + 2];
    g_h1[i * 32 + o] = fmaxf(acc, 0.0f);
}

// -------- layer 2 gather: warp per node, lane = feature (coalesced h1 loads) --------
__global__ void k_gather2() {
    int w = (blockIdx.x * blockDim.x + threadIdx.x) >> 5;
    int lane = threadIdx.x & 31;
    if (w >= N_NODES) return;
    int i = w;
    int cnt = min(g_cur[i], CAP);
    float dc = g_dis[i];

    float acc = dc * dc * g_h1[i * 32 + lane];   // self loop
    for (int base = 0; base < cnt; base += 32) {
        int rem = cnt - base;
        int   r  = (lane < rem) ? g_csr[i * CAP + base + lane] : 0;
        float nm = (lane < rem) ? g_nrm[i * CAP + base + lane] : 0.0f;
        int m = rem < 32 ? rem : 32;
        for (int k = 0; k < m; k++) {
            int   rk  = __shfl_sync(0xffffffff, r, k);
            float nmk = __shfl_sync(0xffffffff, nm, k);
            acc = fmaf(nmk, g_h1[rk * 32 + lane], acc);  // 128B coalesced across warp
        }
    }
    g_agg2[i * 32 + lane] = acc;
}

// -------- layer 2 transform + relu + pooled max (register running-max, 32 nodes/block) --------
#define NPB 32
__global__ void k_transform2_pool(const float* __restrict__ W2,
                                  const float* __restrict__ b2,
                                  const int*   __restrict__ batch) {
    __shared__ float sW2T[32 * 64];     // [k][o] transposed
    __shared__ float sA[2][4 * 32];
    int tid = threadIdx.x;

    for (int x = tid; x < 64 * 32; x += 256) {
        int o = x >> 5, k = x & 31;
        sW2T[k * 64 + o] = W2[x];       // W2 is [64][32] row-major
    }

    int nd = tid >> 6;
    int o  = tid & 63;
    int base = blockIdx.x * NPB;
    float bo = b2[o];

    int   curg = -1;
    float gmax = 0.0f;

#pragma unroll
    for (int j = 0; j < NPB / 4; j++) {
        int i = base + j * 4 + nd;
        int buf = j & 1;
        if (o < 32 && i < N_NODES)
            sA[buf][nd * 32 + o] = g_agg2[i * 32 + o];
        __syncthreads();
        if (i < N_NODES) {
            float acc = bo;
#pragma unroll
            for (int k = 0; k < 32; k++)
                acc = fmaf(sA[buf][nd * 32 + k], sW2T[k * 64 + o], acc);
            acc = fmaxf(acc, 0.0f);
            int g = batch[i];
            if (g != curg) {
                if (curg >= 0)
                    atomicMax(reinterpret_cast<int*>(&g_pooled[curg * 64 + o]),
                              __float_as_int(gmax));
                curg = g;
                gmax = acc;
            } else {
                gmax = fmaxf(gmax, acc);
            }
        }
    }
    if (curg >= 0)
        atomicMax(reinterpret_cast<int*>(&g_pooled[curg * 64 + o]),
                  __float_as_int(gmax));
}

// -------- head: out = pooled @ Wc^T + bc --------
__global__ void k_final(const float* __restrict__ Wc, const float* __restrict__ bc,
                        float* __restrict__ out) {
    int t = blockIdx.x * blockDim.x + threadIdx.x;
    if (t >= N_GRAPHS * 2) return;
    int g = t >> 1;
    int o = t & 1;
    float acc = bc[o];
#pragma unroll
    for (int k = 0; k < 64; k++)
        acc = fmaf(g_pooled[g * 64 + k], Wc[o * 64 + k], acc);
    out[t] = acc;
}

extern "C" void kernel_launch(void* const* d_in, const int* in_sizes, int n_in,
                              void* d_out, int out_size) {
    const float* pos  = (const float*)d_in[0];
    const int*   eidx = (const int*)  d_in[1];
    const int*   bat  = (const int*)  d_in[2];
    const float* W1   = (const float*)d_in[3];
    const float* b1   = (const float*)d_in[4];
    const float* W2   = (const float*)d_in[5];
    const float* b2   = (const float*)d_in[6];
    const float* Wc   = (const float*)d_in[7];
    const float* bc   = (const float*)d_in[8];
    float* out = (float*)d_out;

    const int* row = eidx;             // edge_index[0]
    const int* col = eidx + N_EDGES;   // edge_index[1]

    const int TB = 256;

    k_init <<<(N_NODES + TB - 1) / TB, TB>>>();
    k_build<<<(N_EDGES + TB - 1) / TB, TB>>>(row, col);
    k_dis  <<<(N_NODES + TB - 1) / TB, TB>>>(pos);
    k_gather1<<<(N_NODES * 32 + TB - 1) / TB, TB>>>(W1, b1);
    k_gather2<<<(N_NODES * 32 + TB - 1) / TB, TB>>>();
    k_transform2_pool<<<(N_NODES + NPB - 1) / NPB, TB>>>(W2, b2, bat);
    k_final<<<(N_GRAPHS * 2 + TB - 1) / TB, TB>>>(Wc, bc, out);
}

// round 5
// speedup vs baseline: 1.0197x; 1.0197x over previous
#include <cuda_runtime.h>
#include <cuda_fp16.h>
#include <math.h>

#define N_NODES  100000
#define N_EDGES  3200000
#define N_GRAPHS 256
#define CAP      96        // P(in-degree >= 96) ~ e^-41 per node for Binom(3.2M,1e-5)

// -------- scratch (device globals: no allocations allowed) --------
__device__ int    g_deg[N_NODES];                      // out-degree over row (+1 self)
__device__ int    g_cur[N_NODES];                      // CSR fill cursor -> in-degree
__device__ float  g_dis[N_NODES];
__device__ __align__(16) float g_ps[N_NODES * 4];      // {d*p0, d*p1, d*p2, d}
__device__ int    g_csr[N_NODES * CAP];                // source node per in-edge
__device__ float  g_nrm[N_NODES * CAP];                // norm per in-edge
__device__ __align__(16) __half g_h1h[N_NODES * 32];   // h1 in fp16 (64B/node)
__device__ __align__(16) float g_agg2[N_NODES * 32];
__device__ float  g_pooled[N_GRAPHS * 64];

__device__ __forceinline__ void red_add_s32(int* p, int v) {
    asm volatile("red.global.add.s32 [%0], %1;" :: "l"(p), "r"(v) : "memory");
}

// -------- init: deg=1 (self loop), cur=0, pooled=-inf --------
__global__ void k_init() {
    int t = blockIdx.x * blockDim.x + threadIdx.x;
    if (t < N_NODES) { g_deg[t] = 1; g_cur[t] = 0; }
    if (t < N_GRAPHS * 64) reinterpret_cast<int*>(g_pooled)[t] = 0xFF800000;
}

// -------- build: degree count over row + CSR fill by col --------
__global__ void k_build(const int* __restrict__ row, const int* __restrict__ col) {
    int e = blockIdx.x * blockDim.x + threadIdx.x;
    if (e >= N_EDGES) return;
    int r = row[e], c = col[e];
    red_add_s32(&g_deg[r], 1);
    int loc = atomicAdd(&g_cur[c], 1);
    if (loc < CAP) g_csr[c * CAP + loc] = r;
}

// -------- dis + pos_scaled --------
__global__ void k_dis(const float* __restrict__ pos) {
    int i = blockIdx.x * blockDim.x + threadIdx.x;
    if (i >= N_NODES) return;
    float d = rsqrtf((float)g_deg[i]);
    g_dis[i] = d;
    float p0 = pos[i * 3 + 0], p1 = pos[i * 3 + 1], p2 = pos[i * 3 + 2];
    *reinterpret_cast<float4*>(&g_ps[i * 4]) = make_float4(d * p0, d * p1, d * p2, d);
}

// -------- layer 1 gather + transform fused: warp per node --------
__global__ void k_gather1(const float* __restrict__ W1, const float* __restrict__ b1) {
    int w = (blockIdx.x * blockDim.x + threadIdx.x) >> 5;
    int lane = threadIdx.x & 31;
    if (w >= N_NODES) return;
    int i = w;
    int cnt = min(g_cur[i], CAP);
    float dc = g_dis[i];

    float a0 = 0.f, a1 = 0.f, a2 = 0.f;
    for (int j = lane; j < cnt; j += 32) {
        int r = __ldg(&g_csr[i * CAP + j]);
        float4 ps = *reinterpret_cast<const float4*>(&g_ps[r * 4]);  // {d_r*p, d_r}
        a0 += ps.x; a1 += ps.y; a2 += ps.z;
        g_nrm[i * CAP + j] = dc * ps.w;          // norm for layer-2 reuse
    }
#pragma unroll
    for (int s = 16; s > 0; s >>= 1) {
        a0 += __shfl_xor_sync(0xffffffff, a0, s);
        a1 += __shfl_xor_sync(0xffffffff, a1, s);
        a2 += __shfl_xor_sync(0xffffffff, a2, s);
    }
    // self loop: msg = dc^2 * p_i = dc * ps_i.{x,y,z}
    float4 psc = *reinterpret_cast<const float4*>(&g_ps[i * 4]);
    a0 = dc * (a0 + psc.x);
    a1 = dc * (a1 + psc.y);
    a2 = dc * (a2 + psc.z);

    int o = lane;
    float acc = b1[o] + a0 * W1[o * 3 + 0] + a1 * W1[o * 3 + 1] + a2 * W1[o * 3 + 2];
    g_h1h[i * 32 + o] = __float2half(fmaxf(acc, 0.0f));
}

// -------- layer 2 gather: warp per node, lane = feature; broadcast csr/nrm loads,
//          compile-time unrolled full chunks with 4 accumulators for high MLP --------
__global__ void k_gather2() {
    int w = (blockIdx.x * blockDim.x + threadIdx.x) >> 5;
    int lane = threadIdx.x & 31;
    if (w >= N_NODES) return;
    int i = w;
    int cnt = min(g_cur[i], CAP);
    float dc = g_dis[i];

    const int*   csr = &g_csr[i * CAP];
    const float* nrm = &g_nrm[i * CAP];

    float acc = dc * dc * __half2float(g_h1h[i * 32 + lane]);   // self loop

    int base = 0;
    for (; base + 32 <= cnt; base += 32) {
        float a0 = 0.f, a1 = 0.f, a2 = 0.f, a3 = 0.f;
#pragma unroll
        for (int k = 0; k < 32; k += 4) {
            int   r0 = __ldg(&csr[base + k + 0]);      // uniform: L1 broadcast
            int   r1 = __ldg(&csr[base + k + 1]);
            int   r2 = __ldg(&csr[base + k + 2]);
            int   r3 = __ldg(&csr[base + k + 3]);
            float n0 = __ldg(&nrm[base + k + 0]);
            float n1 = __ldg(&nrm[base + k + 1]);
            float n2 = __ldg(&nrm[base + k + 2]);
            float n3 = __ldg(&nrm[base + k + 3]);
            float h0 = __half2float(g_h1h[r0 * 32 + lane]);  // 64B coalesced/warp
            float h1 = __half2float(g_h1h[r1 * 32 + lane]);
            float h2 = __half2float(g_h1h[r2 * 32 + lane]);
            float h3 = __half2float(g_h1h[r3 * 32 + lane]);
            a0 = fmaf(n0, h0, a0);
            a1 = fmaf(n1, h1, a1);
            a2 = fmaf(n2, h2, a2);
            a3 = fmaf(n3, h3, a3);
        }
        acc += (a0 + a1) + (a2 + a3);
    }
    for (int k = base; k < cnt; k++) {                 // remainder (< 32 edges)
        int   rk = __ldg(&csr[k]);
        float nk = __ldg(&nrm[k]);
        acc = fmaf(nk, __half2float(g_h1h[rk * 32 + lane]), acc);
    }
    g_agg2[i * 32 + lane] = acc;
}

// -------- layer 2 transform + relu + pooled max (register running-max, 32 nodes/block) --------
#define NPB 32
__global__ void k_transform2_pool(const float* __restrict__ W2,
                                  const float* __restrict__ b2,
                                  const int*   __restrict__ batch) {
    __shared__ float sW2T[32 * 64];     // [k][o] transposed
    __shared__ float sA[2][4 * 32];
    int tid = threadIdx.x;

    for (int x = tid; x < 64 * 32; x += 256) {
        int o = x >> 5, k = x & 31;
        sW2T[k * 64 + o] = W2[x];       // W2 is [64][32] row-major
    }

    int nd = tid >> 6;
    int o  = tid & 63;
    int base = blockIdx.x * NPB;
    float bo = b2[o];

    int   curg = -1;
    float gmax = 0.0f;

#pragma unroll
    for (int j = 0; j < NPB / 4; j++) {
        int i = base + j * 4 + nd;
        int buf = j & 1;
        if (o < 32 && i < N_NODES)
            sA[buf][nd * 32 + o] = g_agg2[i * 32 + o];
        __syncthreads();
        if (i < N_NODES) {
            float acc = bo;
#pragma unroll
            for (int k = 0; k < 32; k++)
                acc = fmaf(sA[buf][nd * 32 + k], sW2T[k * 64 + o], acc);
            acc = fmaxf(acc, 0.0f);
            int g = batch[i];
            if (g != curg) {
                if (curg >= 0)
                    atomicMax(reinterpret_cast<int*>(&g_pooled[curg * 64 + o]),
                              __float_as_int(gmax));
                curg = g;
                gmax = acc;
            } else {
                gmax = fmaxf(gmax, acc);
            }
        }
    }
    if (curg >= 0)
        atomicMax(reinterpret_cast<int*>(&g_pooled[curg * 64 + o]),
                  __float_as_int(gmax));
}

// -------- head: out = pooled @ Wc^T + bc --------
__global__ void k_final(const float* __restrict__ Wc, const float* __restrict__ bc,
                        float* __restrict__ out) {
    int t = blockIdx.x * blockDim.x + threadIdx.x;
    if (t >= N_GRAPHS * 2) return;
    int g = t >> 1;
    int o = t & 1;
    float acc = bc[o];
#pragma unroll
    for (int k = 0; k < 64; k++)
        acc = fmaf(g_pooled[g * 64 + k], Wc[o * 64 + k], acc);
    out[t] = acc;
}

extern "C" void kernel_launch(void* const* d_in, const int* in_sizes, int n_in,
                              void* d_out, int out_size) {
    const float* pos  = (const float*)d_in[0];
    const int*   eidx = (const int*)  d_in[1];
    const int*   bat  = (const int*)  d_in[2];
    const float* W1   = (const float*)d_in[3];
    const float* b1   = (const float*)d_in[4];
    const float* W2   = (const float*)d_in[5];
    const float* b2   = (const float*)d_in[6];
    const float* Wc   = (const float*)d_in[7];
    const float* bc   = (const float*)d_in[8];
    float* out = (float*)d_out;

    const int* row = eidx;             // edge_index[0]
    const int* col = eidx + N_EDGES;   // edge_index[1]

    const int TB = 256;

    k_init <<<(N_NODES + TB - 1) / TB, TB>>>();
    k_build<<<(N_EDGES + TB - 1) / TB, TB>>>(row, col);
    k_dis  <<<(N_NODES + TB - 1) / TB, TB>>>(pos);
    k_gather1<<<(N_NODES * 32 + TB - 1) / TB, TB>>>(W1, b1);
    k_gather2<<<(N_NODES * 32 + TB - 1) / TB, TB>>>();
    k_transform2_pool<<<(N_NODES + NPB - 1) / NPB, TB>>>(W2, b2, bat);
    k_final<<<(N_GRAPHS * 2 + TB - 1) / TB, TB>>>(Wc, bc, out);
}

// round 6
// speedup vs baseline: 1.0650x; 1.0444x over previous
#include <cuda_runtime.h>
#include <cuda_fp16.h>
#include <math.h>

#define N_NODES  100000
#define N_EDGES  3200000
#define N_GRAPHS 256
#define CAP      96        // P(in-degree >= 96) ~ e^-41 per node for Binom(3.2M,1e-5)
#define NPW      16        // nodes per warp in fused gather2 kernel

// -------- scratch (device globals: no allocations allowed) --------
__device__ int    g_deg[N_NODES];                      // out-degree over row (+1 self)
__device__ int    g_cur[N_NODES];                      // CSR fill cursor -> in-degree
__device__ float  g_dis[N_NODES];                      // d_i = rsqrt(deg)
__device__ int    g_csr[N_NODES * CAP];                // source node per in-edge
__device__ __align__(16) __half g_z[N_NODES * 32];     // z_i  = W1 @ (d_i * p_i), fp16
__device__ __align__(16) __half g_h1[N_NODES * 32];    // h1'_i = d_i * relu(...), fp16
__device__ float  g_pooled[N_GRAPHS * 64];

__device__ __forceinline__ void red_add_s32(int* p, int v) {
    asm volatile("red.global.add.s32 [%0], %1;" :: "l"(p), "r"(v) : "memory");
}

// sum over CSR neighbors of tbl[r*32 + lane]; coalesced 64B loads, 4 accumulators
__device__ __forceinline__ float gather_sum(const int* __restrict__ csr, int cnt,
                                            const __half* __restrict__ tbl, int lane) {
    float acc = 0.f;
    int base = 0;
    for (; base + 32 <= cnt; base += 32) {
        float a0 = 0.f, a1 = 0.f, a2 = 0.f, a3 = 0.f;
#pragma unroll
        for (int k = 0; k < 32; k += 4) {
            int r0 = __ldg(&csr[base + k + 0]);   // uniform: L1 broadcast
            int r1 = __ldg(&csr[base + k + 1]);
            int r2 = __ldg(&csr[base + k + 2]);
            int r3 = __ldg(&csr[base + k + 3]);
            a0 += __half2float(tbl[r0 * 32 + lane]);
            a1 += __half2float(tbl[r1 * 32 + lane]);
            a2 += __half2float(tbl[r2 * 32 + lane]);
            a3 += __half2float(tbl[r3 * 32 + lane]);
        }
        acc += (a0 + a1) + (a2 + a3);
    }
    for (; base + 4 <= cnt; base += 4) {          // MLP-4 remainder
        int r0 = __ldg(&csr[base + 0]);
        int r1 = __ldg(&csr[base + 1]);
        int r2 = __ldg(&csr[base + 2]);
        int r3 = __ldg(&csr[base + 3]);
        float a0 = __half2float(tbl[r0 * 32 + lane]);
        float a1 = __half2float(tbl[r1 * 32 + lane]);
        float a2 = __half2float(tbl[r2 * 32 + lane]);
        float a3 = __half2float(tbl[r3 * 32 + lane]);
        acc += (a0 + a1) + (a2 + a3);
    }
    for (; base < cnt; base++)
        acc += __half2float(tbl[__ldg(&csr[base]) * 32 + lane]);
    return acc;
}

// -------- init: deg=1 (self loop), cur=0, pooled=-inf --------
__global__ void k_init() {
    int t = blockIdx.x * blockDim.x + threadIdx.x;
    if (t < N_NODES) { g_deg[t] = 1; g_cur[t] = 0; }
    if (t < N_GRAPHS * 64) reinterpret_cast<int*>(g_pooled)[t] = 0xFF800000;
}

// -------- build: 4 edges/thread; deg count over row + CSR fill by col --------
__global__ void k_build(const int4* __restrict__ row4, const int4* __restrict__ col4) {
    int t = blockIdx.x * blockDim.x + threadIdx.x;
    if (t >= N_EDGES / 4) return;
    int4 r = row4[t];
    int4 c = col4[t];
    red_add_s32(&g_deg[r.x], 1);
    red_add_s32(&g_deg[r.y], 1);
    red_add_s32(&g_deg[r.z], 1);
    red_add_s32(&g_deg[r.w], 1);
    int l0 = atomicAdd(&g_cur[c.x], 1);
    int l1 = atomicAdd(&g_cur[c.y], 1);
    int l2 = atomicAdd(&g_cur[c.z], 1);
    int l3 = atomicAdd(&g_cur[c.w], 1);
    if (l0 < CAP) g_csr[c.x * CAP + l0] = r.x;
    if (l1 < CAP) g_csr[c.y * CAP + l1] = r.y;
    if (l2 < CAP) g_csr[c.z * CAP + l2] = r.z;
    if (l3 < CAP) g_csr[c.w * CAP + l3] = r.w;
}

// -------- prep: d = rsqrt(deg); z = W1 @ (d*p), warp per node --------
__global__ void k_prep(const float* __restrict__ pos, const float* __restrict__ W1) {
    int w = (blockIdx.x * blockDim.x + threadIdx.x) >> 5;
    int lane = threadIdx.x & 31;
    if (w >= N_NODES) return;
    float d = rsqrtf((float)g_deg[w]);
    if (lane == 0) g_dis[w] = d;
    float pj = (lane < 3) ? pos[w * 3 + lane] : 0.f;
    float p0 = __shfl_sync(0xffffffff, pj, 0);
    float p1 = __shfl_sync(0xffffffff, pj, 1);
    float p2 = __shfl_sync(0xffffffff, pj, 2);
    float z = d * (p0 * __ldg(&W1[lane * 3 + 0]) +
                   p1 * __ldg(&W1[lane * 3 + 1]) +
                   p2 * __ldg(&W1[lane * 3 + 2]));
    g_z[w * 32 + lane] = __float2half(z);
}

// -------- layer 1: h1' = d * relu(dc*(sum z_r + z_i) + b1), warp per node --------
__global__ void k_gather1(const float* __restrict__ b1) {
    int i = (blockIdx.x * blockDim.x + threadIdx.x) >> 5;
    int lane = threadIdx.x & 31;
    if (i >= N_NODES) return;
    int cnt = min(g_cur[i], CAP);
    float dc = g_dis[i];
    float acc = __half2float(g_z[i * 32 + lane]);           // self loop
    acc += gather_sum(&g_csr[i * CAP], cnt, g_z, lane);
    float pre = fmaf(dc, acc, __ldg(&b1[lane]));
    g_h1[i * 32 + lane] = __float2half(dc * fmaxf(pre, 0.f));
}

// -------- layer 2 gather + transform + relu + pooled max, fully fused --------
__global__ void __launch_bounds__(256) k_g2pool(const float* __restrict__ W2,
                                                const float* __restrict__ b2,
                                                const int*   __restrict__ batch) {
    __shared__ float sW2T[32 * 64];     // [k][o]
    __shared__ float sAgg[8][32];       // warp-private staging
    int tid = threadIdx.x;
    for (int x = tid; x < 64 * 32; x += 256) {
        int o = x >> 5, k = x & 31;
        sW2T[k * 64 + o] = W2[x];       // W2 is [64][32] row-major
    }
    __syncthreads();

    int warp = (blockIdx.x * blockDim.x + tid) >> 5;
    int wloc = tid >> 5;
    int lane = tid & 31;
    int base = warp * NPW;
    if (base >= N_NODES) return;

    float bo0 = __ldg(&b2[lane]);
    float bo1 = __ldg(&b2[lane + 32]);

    int   curg = -1;
    float m0 = 0.f, m1 = 0.f;           // relu >= 0: safe identity

    for (int t = 0; t < NPW; t++) {
        int i = base + t;
        if (i >= N_NODES) break;
        int cnt = min(g_cur[i], CAP);
        float acc = __half2float(g_h1[i * 32 + lane]);      // self loop
        acc += gather_sum(&g_csr[i * CAP], cnt, g_h1, lane);
        sAgg[wloc][lane] = g_dis[i] * acc;                  // agg2[k], k = lane
        __syncwarp();
        float acc0 = bo0, acc1 = bo1;
#pragma unroll
        for (int k = 0; k < 32; k++) {
            float a = sAgg[wloc][k];
            acc0 = fmaf(a, sW2T[k * 64 + lane],      acc0);
            acc1 = fmaf(a, sW2T[k * 64 + lane + 32], acc1);
        }
        __syncwarp();
        acc0 = fmaxf(acc0, 0.f);
        acc1 = fmaxf(acc1, 0.f);
        int g = batch[i];
        if (g != curg) {
            if (curg >= 0) {
                atomicMax(reinterpret_cast<int*>(&g_pooled[curg * 64 + lane]),
                          __float_as_int(m0));
                atomicMax(reinterpret_cast<int*>(&g_pooled[curg * 64 + lane + 32]),
                          __float_as_int(m1));
            }
            curg = g; m0 = acc0; m1 = acc1;
        } else {
            m0 = fmaxf(m0, acc0);
            m1 = fmaxf(m1, acc1);
        }
    }
    if (curg >= 0) {
        atomicMax(reinterpret_cast<int*>(&g_pooled[curg * 64 + lane]),
                  __float_as_int(m0));
        atomicMax(reinterpret_cast<int*>(&g_pooled[curg * 64 + lane + 32]),
                  __float_as_int(m1));
    }
}

// -------- head: out = pooled @ Wc^T + bc --------
__global__ void k_final(const float* __restrict__ Wc, const float* __restrict__ bc,
                        float* __restrict__ out) {
    int t = blockIdx.x * blockDim.x + threadIdx.x;
    if (t >= N_GRAPHS * 2) return;
    int g = t >> 1;
    int o = t & 1;
    float acc = bc[o];
#pragma unroll
    for (int k = 0; k < 64; k++)
        acc = fmaf(g_pooled[g * 64 + k], Wc[o * 64 + k], acc);
    out[t] = acc;
}

extern "C" void kernel_launch(void* const* d_in, const int* in_sizes, int n_in,
                              void* d_out, int out_size) {
    const float* pos  = (const float*)d_in[0];
    const int*   eidx = (const int*)  d_in[1];
    const int*   bat  = (const int*)  d_in[2];
    const float* W1   = (const float*)d_in[3];
    const float* b1   = (const float*)d_in[4];
    const float* W2   = (const float*)d_in[5];
    const float* b2   = (const float*)d_in[6];
    const float* Wc   = (const float*)d_in[7];
    const float* bc   = (const float*)d_in[8];
    float* out = (float*)d_out;

    const int* row = eidx;             // edge_index[0]
    const int* col = eidx + N_EDGES;   // edge_index[1]

    const int TB = 256;

    k_init <<<(N_NODES + TB - 1) / TB, TB>>>();
    k_build<<<(N_EDGES / 4 + TB - 1) / TB, TB>>>((const int4*)row, (const int4*)col);
    k_prep <<<(N_NODES * 32 + TB - 1) / TB, TB>>>(pos, W1);
    k_gather1<<<(N_NODES * 32 + TB - 1) / TB, TB>>>(b1);
    {
        int warps = (N_NODES + NPW - 1) / NPW;
        int blocks = (warps * 32 + TB - 1) / TB;
        k_g2pool<<<blocks, TB>>>(W2, b2, bat);
    }
    k_final<<<(N_GRAPHS * 2 + TB - 1) / TB, TB>>>(Wc, bc, out);
}

// round 7
// speedup vs baseline: 1.1063x; 1.0388x over previous
#include <cuda_runtime.h>
#include <cuda_fp16.h>
#include <math.h>

#define N_NODES  100000
#define N_EDGES  3200000
#define N_GRAPHS 256
#define CAP      96        // P(in-degree >= 96) ~ e^-41 per node for Binom(3.2M,1e-5)
#define NPW      16        // nodes per warp in fused gather2 kernel

// -------- scratch (device globals: no allocations allowed) --------
__device__ int    g_deg[N_NODES];                      // out-degree over row (+1 self)
__device__ int    g_cur[N_NODES];                      // CSR fill cursor -> in-degree
__device__ float  g_dis[N_NODES];                      // d_i = rsqrt(deg)
__device__ __align__(16) int g_csr[N_NODES * CAP];     // source node per in-edge (row base 384B)
__device__ __align__(16) __half g_z[N_NODES * 32];     // z_i  = W1 @ (d_i * p_i), fp16
__device__ __align__(16) __half g_h1[N_NODES * 32];    // h1'_i = d_i * relu(...), fp16
__device__ float  g_pooled[N_GRAPHS * 64];

__device__ __forceinline__ void red_add_s32(int* p, int v) {
    asm volatile("red.global.add.s32 [%0], %1;" :: "l"(p), "r"(v) : "memory");
}

// Paired-edge gather: lanes 0-15 take even edges, 16-31 odd edges; each lane
// loads a half2 (features 2*sub, 2*sub+1). fp32 accumulation. Returns the
// per-feature sum with lane = feature (0..31).
__device__ __forceinline__ float gather_sum_h2(const int* __restrict__ csr, int cnt,
                                               const __half* __restrict__ tbl, int lane) {
    const int grp = lane >> 4;          // 0: even edge of pair, 1: odd edge
    const int sub = lane & 15;          // feature-pair index
    const __half2* t2 = reinterpret_cast<const __half2*>(tbl);  // 16 half2 per row
    float ax = 0.f, ay = 0.f;

    int p = 0;
#pragma unroll 4
    for (; p + 4 <= cnt; p += 4) {
        int4 q = *reinterpret_cast<const int4*>(csr + p);   // 16B-aligned (row=384B, p%4==0)
        int ra = grp ? q.y : q.x;
        int rb = grp ? q.w : q.z;
        float2 fa = __half22float2(__ldg(&t2[ra * 16 + sub]));
        float2 fb = __half22float2(__ldg(&t2[rb * 16 + sub]));
        ax += fa.x + fb.x;
        ay += fa.y + fb.y;
    }
    if (p + 2 <= cnt) {
        int2 q = *reinterpret_cast<const int2*>(csr + p);
        int ra = grp ? q.y : q.x;
        float2 fa = __half22float2(__ldg(&t2[ra * 16 + sub]));
        ax += fa.x;
        ay += fa.y;
        p += 2;
    }
    if (p < cnt && grp == 0) {          // single leftover edge: group 0 only
        int ra = __ldg(&csr[p]);
        float2 fa = __half22float2(__ldg(&t2[ra * 16 + sub]));
        ax += fa.x;
        ay += fa.y;
    }
    // combine even/odd groups
    ax += __shfl_xor_sync(0xffffffff, ax, 16);
    ay += __shfl_xor_sync(0xffffffff, ay, 16);
    // redistribute: feature f = lane lives in pair-slot (lane>>1), x/y by parity
    float vx = __shfl_sync(0xffffffff, ax, lane >> 1);
    float vy = __shfl_sync(0xffffffff, ay, lane >> 1);
    return (lane & 1) ? vy : vx;
}

// -------- init: deg=1 (self loop), cur=0, pooled=-inf --------
__global__ void k_init() {
    int t = blockIdx.x * blockDim.x + threadIdx.x;
    if (t < N_NODES) { g_deg[t] = 1; g_cur[t] = 0; }
    if (t < N_GRAPHS * 64) reinterpret_cast<int*>(g_pooled)[t] = 0xFF800000;
}

// -------- build: 4 edges/thread; deg count over row + CSR fill by col --------
__global__ void k_build(const int4* __restrict__ row4, const int4* __restrict__ col4) {
    int t = blockIdx.x * blockDim.x + threadIdx.x;
    if (t >= N_EDGES / 4) return;
    int4 r = row4[t];
    int4 c = col4[t];
    red_add_s32(&g_deg[r.x], 1);
    red_add_s32(&g_deg[r.y], 1);
    red_add_s32(&g_deg[r.z], 1);
    red_add_s32(&g_deg[r.w], 1);
    int l0 = atomicAdd(&g_cur[c.x], 1);
    int l1 = atomicAdd(&g_cur[c.y], 1);
    int l2 = atomicAdd(&g_cur[c.z], 1);
    int l3 = atomicAdd(&g_cur[c.w], 1);
    if (l0 < CAP) g_csr[c.x * CAP + l0] = r.x;
    if (l1 < CAP) g_csr[c.y * CAP + l1] = r.y;
    if (l2 < CAP) g_csr[c.z * CAP + l2] = r.z;
    if (l3 < CAP) g_csr[c.w * CAP + l3] = r.w;
}

// -------- prep: d = rsqrt(deg); z = W1 @ (d*p), warp per node --------
__global__ void k_prep(const float* __restrict__ pos, const float* __restrict__ W1) {
    int w = (blockIdx.x * blockDim.x + threadIdx.x) >> 5;
    int lane = threadIdx.x & 31;
    if (w >= N_NODES) return;
    float d = rsqrtf((float)g_deg[w]);
    if (lane == 0) g_dis[w] = d;
    float pj = (lane < 3) ? pos[w * 3 + lane] : 0.f;
    float p0 = __shfl_sync(0xffffffff, pj, 0);
    float p1 = __shfl_sync(0xffffffff, pj, 1);
    float p2 = __shfl_sync(0xffffffff, pj, 2);
    float z = d * (p0 * __ldg(&W1[lane * 3 + 0]) +
                   p1 * __ldg(&W1[lane * 3 + 1]) +
                   p2 * __ldg(&W1[lane * 3 + 2]));
    g_z[w * 32 + lane] = __float2half(z);
}

// -------- layer 1: h1' = d * relu(dc*(sum z_r + z_i) + b1), warp per node --------
__global__ void k_gather1(const float* __restrict__ b1) {
    int i = (blockIdx.x * blockDim.x + threadIdx.x) >> 5;
    int lane = threadIdx.x & 31;
    if (i >= N_NODES) return;
    int cnt = min(g_cur[i], CAP);
    float dc = g_dis[i];
    float acc = __half2float(g_z[i * 32 + lane]);           // self loop
    acc += gather_sum_h2(&g_csr[i * CAP], cnt, g_z, lane);
    float pre = fmaf(dc, acc, __ldg(&b1[lane]));
    g_h1[i * 32 + lane] = __float2half(dc * fmaxf(pre, 0.f));
}

// -------- layer 2 gather + transform + relu + pooled max, fully fused --------
__global__ void __launch_bounds__(256) k_g2pool(const float* __restrict__ W2,
                                                const float* __restrict__ b2,
                                                const int*   __restrict__ batch) {
    __shared__ float2 sW2[32 * 32];     // [k][o] = {W2T[k][o], W2T[k][o+32]}
    int tid = threadIdx.x;
    for (int x = tid; x < 32 * 32; x += 256) {
        int k = x >> 5, o = x & 31;
        sW2[k * 32 + o] = make_float2(W2[o * 32 + k], W2[(o + 32) * 32 + k]);
    }
    __syncthreads();

    int warp = (blockIdx.x * blockDim.x + tid) >> 5;
    int lane = tid & 31;
    int base = warp * NPW;
    if (base >= N_NODES) return;

    float bo0 = __ldg(&b2[lane]);
    float bo1 = __ldg(&b2[lane + 32]);

    int   curg = -1;
    float m0 = 0.f, m1 = 0.f;           // relu >= 0: safe identity

    for (int t = 0; t < NPW; t++) {
        int i = base + t;
        if (i >= N_NODES) break;
        int cnt = min(g_cur[i], CAP);
        float acc = __half2float(g_h1[i * 32 + lane]);      // self loop
        acc += gather_sum_h2(&g_csr[i * CAP], cnt, g_h1, lane);
        float agg = g_dis[i] * acc;                         // agg2[lane]

        float acc0 = bo0, acc1 = bo1;
#pragma unroll
        for (int k = 0; k < 32; k++) {
            float a = __shfl_sync(0xffffffff, agg, k);
            float2 w = sW2[k * 32 + lane];
            acc0 = fmaf(a, w.x, acc0);
            acc1 = fmaf(a, w.y, acc1);
        }
        acc0 = fmaxf(acc0, 0.f);
        acc1 = fmaxf(acc1, 0.f);
        int g = batch[i];
        if (g != curg) {
            if (curg >= 0) {
                atomicMax(reinterpret_cast<int*>(&g_pooled[curg * 64 + lane]),
                          __float_as_int(m0));
                atomicMax(reinterpret_cast<int*>(&g_pooled[curg * 64 + lane + 32]),
                          __float_as_int(m1));
            }
            curg = g; m0 = acc0; m1 = acc1;
        } else {
            m0 = fmaxf(m0, acc0);
            m1 = fmaxf(m1, acc1);
        }
    }
    if (curg >= 0) {
        atomicMax(reinterpret_cast<int*>(&g_pooled[curg * 64 + lane]),
                  __float_as_int(m0));
        atomicMax(reinterpret_cast<int*>(&g_pooled[curg * 64 + lane + 32]),
                  __float_as_int(m1));
    }
}

// -------- head: out = pooled @ Wc^T + bc --------
__global__ void k_final(const float* __restrict__ Wc, const float* __restrict__ bc,
                        float* __restrict__ out) {
    int t = blockIdx.x * blockDim.x + threadIdx.x;
    if (t >= N_GRAPHS * 2) return;
    int g = t >> 1;
    int o = t & 1;
    float acc = bc[o];
#pragma unroll
    for (int k = 0; k < 64; k++)
        acc = fmaf(g_pooled[g * 64 + k], Wc[o * 64 + k], acc);
    out[t] = acc;
}

extern "C" void kernel_launch(void* const* d_in, const int* in_sizes, int n_in,
                              void* d_out, int out_size) {
    const float* pos  = (const float*)d_in[0];
    const int*   eidx = (const int*)  d_in[1];
    const int*   bat  = (const int*)  d_in[2];
    const float* W1   = (const float*)d_in[3];
    const float* b1   = (const float*)d_in[4];
    const float* W2   = (const float*)d_in[5];
    const float* b2   = (const float*)d_in[6];
    const float* Wc   = (const float*)d_in[7];
    const float* bc   = (const float*)d_in[8];
    float* out = (float*)d_out;

    const int* row = eidx;             // edge_index[0]
    const int* col = eidx + N_EDGES;   // edge_index[1]

    const int TB = 256;

    k_init <<<(N_NODES + TB - 1) / TB, TB>>>();
    k_build<<<(N_EDGES / 4 + TB - 1) / TB, TB>>>((const int4*)row, (const int4*)col);
    k_prep <<<(N_NODES * 32 + TB - 1) / TB, TB>>>(pos, W1);
    k_gather1<<<(N_NODES * 32 + TB - 1) / TB, TB>>>(b1);
    {
        int warps = (N_NODES + NPW - 1) / NPW;
        int blocks = (warps * 32 + TB - 1) / TB;
        k_g2pool<<<blocks, TB>>>(W2, b2, bat);
    }
    k_final<<<(N_GRAPHS * 2 + TB - 1) / TB, TB>>>(Wc, bc, out);
}